// round 15
// baseline (speedup 1.0000x reference)
#include <cuda_runtime.h>
#include <cuda_bf16.h>

#define N_NODES 50000
#define N_EDGES 800000
#define IN_DIM  128
#define HID     64
#define N_GRAPHS 64
#define MAXDEG  64   // P(Poisson(16) > 64) ~ 1e-17 per node; safe

// ---------------- device scratch ----------------
// INVARIANT at entry to kernel_launch (established at module load, restored by
// the fused-final block in k_agg2f every call): g_deg == 0, g_pool == 0,
// g_cnt == 0, g_c1 == 0, g_c2 == 0.
__device__ float g_g[N_NODES * HID];      // GEMM output payload (both layers)
__device__ float g_a[N_NODES * HID];      // conv1 activation
__device__ int   g_deg[N_NODES];
__device__ int   g_adj[N_NODES * MAXDEG]; // bucket adjacency: sources per target
__device__ int   g_batch[N_NODES];
__device__ float g_pool[N_GRAPHS * HID];
__device__ int   g_cnt[N_GRAPHS];
__device__ int   g_c1;                    // conv1 prep-phase arrive counter
__device__ int   g_c2;                    // agg2 completion counter

#define GK  32     // K chunk
#define GNT 128    // node tile
#define GNP 132    // padded stride for sxT rows
#define GB1 ((N_NODES + GNT - 1) / GNT)   // 391 blocks for both GEMMs
#define AGG_BLOCKS (N_NODES / 8)          // 6250 blocks, 8 nodes (warps) each

#define SPLAT2(dst, s) asm("mov.b64 %0, {%1,%1};" : "=l"(dst) : "r"(__float_as_uint(s)))
#define FMA2(acc, a, b) asm("fma.rn.f32x2 %0, %1, %2, %0;" : "+l"(acc) : "l"(a), "l"(b))
#define UNPACKF(a, b, src) asm("mov.b64 {%0, %1}, %2;" : "=f"(a), "=f"(b) : "l"(src))

// ---------------- shared GEMM main loop (reads only X, W) ----------------
template<int K>
__device__ __forceinline__ void gemm_main(const float* __restrict__ X,
                                          const float* __restrict__ W,
                                          float (*sxT)[GNP], float* sW,
                                          int n0, int tx, int ty8,
                                          unsigned long long* accA, unsigned long long* accB) {
    int t = threadIdx.x;
    for (int kc = 0; kc < K; kc += GK) {
        {
            const float4* Wg = (const float4*)(W + kc * HID);
            float4* sW4 = (float4*)sW;
            sW4[t]       = Wg[t];
            sW4[t + 256] = Wg[t + 256];
        }
        #pragma unroll
        for (int j = t; j < 1024; j += 256) {
            int node = j >> 3;
            int k4 = (j & 7) * 4;
            int gn = n0 + node;
            float4 v = (gn < N_NODES) ? ((const float4*)(X + gn * K + kc))[j & 7]
                                      : make_float4(0.f, 0.f, 0.f, 0.f);
            sxT[k4 + 0][node] = v.x;
            sxT[k4 + 1][node] = v.y;
            sxT[k4 + 2][node] = v.z;
            sxT[k4 + 3][node] = v.w;
        }
        __syncthreads();
        const float4* sW4 = (const float4*)sW;
        #pragma unroll 8
        for (int k = 0; k < GK; k++) {
            float4 w = sW4[k * 16 + tx];
            unsigned long long w01, w23;
            asm("mov.b64 %0, {%1,%2};" : "=l"(w01) : "f"(w.x), "f"(w.y));
            asm("mov.b64 %0, {%1,%2};" : "=l"(w23) : "f"(w.z), "f"(w.w));
            float4 xa = *(const float4*)(&sxT[k][ty8]);
            float4 xb = *(const float4*)(&sxT[k][ty8 + 4]);
            unsigned long long xx;
            SPLAT2(xx, xa.x); FMA2(accA[0], w01, xx); FMA2(accB[0], w23, xx);
            SPLAT2(xx, xa.y); FMA2(accA[1], w01, xx); FMA2(accB[1], w23, xx);
            SPLAT2(xx, xa.z); FMA2(accA[2], w01, xx); FMA2(accB[2], w23, xx);
            SPLAT2(xx, xa.w); FMA2(accA[3], w01, xx); FMA2(accB[3], w23, xx);
            SPLAT2(xx, xb.x); FMA2(accA[4], w01, xx); FMA2(accB[4], w23, xx);
            SPLAT2(xx, xb.y); FMA2(accA[5], w01, xx); FMA2(accB[5], w23, xx);
            SPLAT2(xx, xb.z); FMA2(accA[6], w01, xx); FMA2(accB[6], w23, xx);
            SPLAT2(xx, xb.w); FMA2(accA[7], w01, xx); FMA2(accB[7], w23, xx);
        }
        __syncthreads();
    }
}

__device__ __forceinline__ void gemm_epilogue(int n0, int tx, int ty8,
                                              const unsigned long long* accA,
                                              const unsigned long long* accB) {
    #pragma unroll
    for (int i = 0; i < 8; i++) {
        int n = n0 + ty8 + i;
        if (n < N_NODES) {
            float dc = rsqrtf((float)(g_deg[n] + 1));
            float f0, f1, f2, f3;
            UNPACKF(f0, f1, accA[i]);
            UNPACKF(f2, f3, accB[i]);
            ((float4*)g_g)[n * 16 + tx] = make_float4(f0 * dc, f1 * dc, f2 * dc, f3 * dc);
        }
    }
}

// ---------------- conv1 = prep (grid-stride slice) + device barrier + gemm1 ----------------
// Barrier is deadlock-free: 391 blocks @ 64 regs/25KB smem/256thr -> 4 blocks/SM
// (592 concurrent capacity on 148+ SMs), so all blocks are resident in wave 1.
__global__ void __launch_bounds__(256, 4)
k_conv1(const float* __restrict__ x, const float* __restrict__ W1,
        const void* __restrict__ ei, const void* __restrict__ batch) {
    __shared__ float sxT[GK][GNP];
    __shared__ float sW[GK * HID];
    int t = threadIdx.x;

    // ---- phase 1: prep slice ----
    __shared__ int s_any;
    if (t == 0) s_any = 0;
    __syncthreads();
    {
        const int* p32 = (const int*)ei;
        int v = p32[2 * t + 1];   // ids < 50000: int64 => odd words all zero
        if (v) atomicOr(&s_any, 1);
    }
    __syncthreads();
    int is64 = (s_any == 0) ? 1 : 0;

    const int NT = GB1 * 256;
    for (int e = blockIdx.x * 256 + t; e < N_EDGES; e += NT) {
        int r, c;
        if (is64) {
            const long long* p = (const long long*)ei;
            r = (int)p[e];
            c = (int)p[N_EDGES + e];
        } else {
            const int* p = (const int*)ei;
            r = p[e];
            c = p[N_EDGES + e];
        }
        int pos = atomicAdd(&g_deg[c], 1);
        if (pos < MAXDEG) g_adj[c * MAXDEG + pos] = r;
    }
    for (int i = blockIdx.x * 256 + t; i < N_NODES; i += NT) {
        int b = is64 ? (int)((const long long*)batch)[i] : ((const int*)batch)[i];
        g_batch[i] = b;
        atomicAdd(&g_cnt[b], 1);
    }
    __threadfence();          // release adj/batch/deg writes
    __syncthreads();
    if (t == 0) atomicAdd(&g_c1, 1);

    // ---- phase 2: GEMM main loop (inputs only; overlaps other blocks' prep) ----
    int n0 = blockIdx.x * GNT;
    int tx = t & 15;
    int ty8 = (t >> 4) * 8;
    unsigned long long accA[8], accB[8];
    #pragma unroll
    for (int i = 0; i < 8; i++) { accA[i] = 0ULL; accB[i] = 0ULL; }
    gemm_main<IN_DIM>(x, W1, sxT, sW, n0, tx, ty8, accA, accB);

    // ---- phase 3: wait for all prep slices, then deg-dependent epilogue ----
    if (t == 0) {
        while (atomicAdd(&g_c1, 0) < GB1) __nanosleep(64);
    }
    __syncthreads();
    __threadfence();          // acquire
    gemm_epilogue(n0, tx, ty8, accA, accB);
}

// ---------------- gemm2 (plain): g_g = dinv * (g_a @ W2) ----------------
__global__ void __launch_bounds__(256, 4)
k_gemm2(const float* __restrict__ W2) {
    __shared__ float sxT[GK][GNP];
    __shared__ float sW[GK * HID];
    int t = threadIdx.x;
    int n0 = blockIdx.x * GNT;
    int tx = t & 15;
    int ty8 = (t >> 4) * 8;
    unsigned long long accA[8], accB[8];
    #pragma unroll
    for (int i = 0; i < 8; i++) { accA[i] = 0ULL; accB[i] = 0ULL; }
    gemm_main<HID>((const float*)g_a, W2, sxT, sW, n0, tx, ty8, accA, accB);
    gemm_epilogue(n0, tx, ty8, accA, accB);
}

// ---------------- gather (R10-proven plain float4 form) ----------------
__device__ __forceinline__ float4 gather_region(const float4* __restrict__ G4, int fq, int half,
                                                int areg, int len, float4 acc) {
    int i = 0;
    for (; i + 8 <= len; i += 8) {
        int e0 = __shfl_sync(0xFFFFFFFFu, areg, i + 0 + half);
        int e1 = __shfl_sync(0xFFFFFFFFu, areg, i + 2 + half);
        int e2 = __shfl_sync(0xFFFFFFFFu, areg, i + 4 + half);
        int e3 = __shfl_sync(0xFFFFFFFFu, areg, i + 6 + half);
        float4 v0 = G4[e0 * 16 + fq];
        float4 v1 = G4[e1 * 16 + fq];
        float4 v2 = G4[e2 * 16 + fq];
        float4 v3 = G4[e3 * 16 + fq];
        acc.x += (v0.x + v1.x) + (v2.x + v3.x);
        acc.y += (v0.y + v1.y) + (v2.y + v3.y);
        acc.z += (v0.z + v1.z) + (v2.z + v3.z);
        acc.w += (v0.w + v1.w) + (v2.w + v3.w);
    }
    for (; i + 2 <= len; i += 2) {
        int e = __shfl_sync(0xFFFFFFFFu, areg, i + half);
        float4 v = G4[e * 16 + fq];
        acc.x += v.x; acc.y += v.y; acc.z += v.z; acc.w += v.w;
    }
    if (i < len) {
        int e = __shfl_sync(0xFFFFFFFFu, areg, i);
        if (half == 0) {
            float4 v = G4[e * 16 + fq];
            acc.x += v.x; acc.y += v.y; acc.z += v.z; acc.w += v.w;
        }
    }
    return acc;
}

__device__ __forceinline__ float4 gather_sum4(int node, int lane, int d) {
    int half = lane >> 4;
    int fq   = lane & 15;
    const float4* G4 = (const float4*)g_g;
    const int* adj = &g_adj[node * MAXDEG];
    int a0 = (lane < d)      ? adj[lane]      : 0;
    int a1 = (32 + lane < d) ? adj[32 + lane] : 0;
    float4 acc = make_float4(0.f, 0.f, 0.f, 0.f);
    if (half == 0) acc = G4[node * 16 + fq];
    int d0 = min(d, 32);
    acc = gather_region(G4, fq, half, a0, d0, acc);
    if (d > 32) acc = gather_region(G4, fq, half, a1, d - 32, acc);
    acc.x += __shfl_xor_sync(0xFFFFFFFFu, acc.x, 16);
    acc.y += __shfl_xor_sync(0xFFFFFFFFu, acc.y, 16);
    acc.z += __shfl_xor_sync(0xFFFFFFFFu, acc.z, 16);
    acc.w += __shfl_xor_sync(0xFFFFFFFFu, acc.w, 16);
    return acc;
}

// ---------------- agg1: gather over g_g + relu -> g_a ----------------
__global__ void k_agg1(const float* __restrict__ b) {
    int warp = (blockIdx.x * blockDim.x + threadIdx.x) >> 5;
    if (warp >= N_NODES) return;
    int lane = threadIdx.x & 31;
    int d = min(g_deg[warp], MAXDEG);
    float4 acc = gather_sum4(warp, lane, d);
    if (lane < 16) {
        float dc = rsqrtf((float)(d + 1));
        float4 bb = ((const float4*)b)[lane];
        float4 o;
        o.x = fmaxf(acc.x * dc + bb.x, 0.f);
        o.y = fmaxf(acc.y * dc + bb.y, 0.f);
        o.z = fmaxf(acc.z * dc + bb.z, 0.f);
        o.w = fmaxf(acc.w * dc + bb.w, 0.f);
        ((float4*)g_a)[warp * 16 + lane] = o;
    }
}

// ---------------- agg2 + fused final (last-block pattern) ----------------
__global__ void k_agg2f(const float* __restrict__ b,
                        const float* __restrict__ Wl, const float* __restrict__ bl,
                        float* __restrict__ out) {
    int warp = blockIdx.x * 8 + (threadIdx.x >> 5);   // grid is exactly N_NODES/8 blocks
    int lane = threadIdx.x & 31;
    int d = min(g_deg[warp], MAXDEG);
    float4 acc = gather_sum4(warp, lane, d);
    if (lane < 16) {
        float dc = rsqrtf((float)(d + 1));
        float4 bb = ((const float4*)b)[lane];
        float ox = fmaxf(acc.x * dc + bb.x, 0.f);
        float oy = fmaxf(acc.y * dc + bb.y, 0.f);
        float oz = fmaxf(acc.z * dc + bb.z, 0.f);
        float ow = fmaxf(acc.w * dc + bb.w, 0.f);
        int gid = g_batch[warp];
        float* dst = &g_pool[gid * HID + lane * 4];
        asm volatile("red.global.add.v4.f32 [%0], {%1,%2,%3,%4};"
                     :: "l"(dst), "f"(ox), "f"(oy), "f"(oz), "f"(ow) : "memory");
    }
    // restore deg invariant for the node this warp owns (sole reader)
    if (lane == 0) g_deg[warp] = 0;

    // completion counter; last block runs the head + restores remaining invariants
    __shared__ int s_rank;
    __threadfence();
    __syncthreads();
    if (threadIdx.x == 0) s_rank = atomicAdd(&g_c2, 1);
    __syncthreads();
    if (s_rank != AGG_BLOCKS - 1) return;
    __threadfence();   // acquire: all other blocks' REDs visible in L2

    int t = threadIdx.x;
    if (t < N_GRAPHS) {
        int gph = t;
        int cnti;
        asm("ld.global.cg.s32 %0, [%1];" : "=r"(cnti) : "l"(&g_cnt[gph]));
        float cnt = fmaxf((float)cnti, 1.f);
        float inv = 1.f / cnt;
        float l0 = bl[0], l1 = bl[1];
        #pragma unroll
        for (int k = 0; k < HID; k++) {
            float p;
            asm("ld.global.cg.f32 %0, [%1];" : "=f"(p) : "l"(&g_pool[gph * HID + k]));
            p *= inv;
            l0 += p * Wl[k * 2 + 0];
            l1 += p * Wl[k * 2 + 1];
        }
        float m = fmaxf(l0, l1);
        float lse = m + logf(expf(l0 - m) + expf(l1 - m));
        out[gph * 2 + 0] = l0 - lse;
        out[gph * 2 + 1] = l1 - lse;
        g_cnt[gph] = 0;
    }
    __syncthreads();
    // zero pool (1024 float4 over 256 threads) + reset counters
    float4 z4 = make_float4(0.f, 0.f, 0.f, 0.f);
    #pragma unroll
    for (int j = 0; j < 4; j++) ((float4*)g_pool)[t + j * 256] = z4;
    if (t == 0) { g_c1 = 0; g_c2 = 0; }
}

extern "C" void kernel_launch(void* const* d_in, const int* in_sizes, int n_in,
                              void* d_out, int out_size) {
    const float* x  = (const float*)d_in[0];
    const void*  ei = d_in[1];
    const void*  bt = d_in[2];
    const float* W1 = (const float*)d_in[3];
    const float* b1 = (const float*)d_in[4];
    const float* W2 = (const float*)d_in[5];
    const float* b2 = (const float*)d_in[6];
    const float* Wl = (const float*)d_in[7];
    const float* bl = (const float*)d_in[8];
    float* out = (float*)d_out;

    // conv1: prep + barrier + linear (x @ W1, pre-scaled)
    k_conv1<<<GB1, 256>>>(x, W1, ei, bt);
    // conv1 aggregate + relu
    k_agg1<<<(N_NODES * 32 + 255) / 256, 256>>>(b1);
    // conv2 linear
    k_gemm2<<<GB1, 256>>>(W2);
    // conv2 aggregate + relu + pool + fused head/cleanup
    k_agg2f<<<AGG_BLOCKS, 256>>>(b2, Wl, bl, out);
}

// round 16
// speedup vs baseline: 1.1133x; 1.1133x over previous
#include <cuda_runtime.h>
#include <cuda_bf16.h>

#define N_NODES 50000
#define N_EDGES 800000
#define IN_DIM  128
#define HID     64
#define N_GRAPHS 64
#define MAXDEG  64   // P(Poisson(16) > 64) ~ 1e-17 per node; safe

// ---------------- device scratch ----------------
// INVARIANT at entry to kernel_launch (established at module load, restored by
// k_final every call): g_deg == 0, g_pool == 0, g_cnt == 0, g_c1 == 0.
__device__ float g_g[N_NODES * HID];      // GEMM output payload (both layers)
__device__ float g_a[N_NODES * HID];      // conv1 activation
__device__ int   g_deg[N_NODES];
__device__ int   g_adj[N_NODES * MAXDEG]; // bucket adjacency: sources per target
__device__ int   g_batch[N_NODES];
__device__ float g_pool[N_GRAPHS * HID];
__device__ int   g_cnt[N_GRAPHS];
__device__ int   g_c1;                    // conv1 prep-phase arrive counter

#define GK  32     // K chunk
#define GNT 128    // node tile
#define GNP 132    // padded stride for sxT rows
#define GB1 ((N_NODES + GNT - 1) / GNT)   // 391 blocks for both GEMMs

#define SPLAT2(dst, s) asm("mov.b64 %0, {%1,%1};" : "=l"(dst) : "r"(__float_as_uint(s)))
#define FMA2(acc, a, b) asm("fma.rn.f32x2 %0, %1, %2, %0;" : "+l"(acc) : "l"(a), "l"(b))
#define UNPACKF(a, b, src) asm("mov.b64 {%0, %1}, %2;" : "=f"(a), "=f"(b) : "l"(src))

// ---------------- shared GEMM main loop (reads only X, W) ----------------
template<int K>
__device__ __forceinline__ void gemm_main(const float* __restrict__ X,
                                          const float* __restrict__ W,
                                          float (*sxT)[GNP], float* sW,
                                          int n0, int tx, int ty8,
                                          unsigned long long* accA, unsigned long long* accB) {
    int t = threadIdx.x;
    for (int kc = 0; kc < K; kc += GK) {
        {
            const float4* Wg = (const float4*)(W + kc * HID);
            float4* sW4 = (float4*)sW;
            sW4[t]       = Wg[t];
            sW4[t + 256] = Wg[t + 256];
        }
        #pragma unroll
        for (int j = t; j < 1024; j += 256) {
            int node = j >> 3;
            int k4 = (j & 7) * 4;
            int gn = n0 + node;
            float4 v = (gn < N_NODES) ? ((const float4*)(X + gn * K + kc))[j & 7]
                                      : make_float4(0.f, 0.f, 0.f, 0.f);
            sxT[k4 + 0][node] = v.x;
            sxT[k4 + 1][node] = v.y;
            sxT[k4 + 2][node] = v.z;
            sxT[k4 + 3][node] = v.w;
        }
        __syncthreads();
        const float4* sW4 = (const float4*)sW;
        #pragma unroll 8
        for (int k = 0; k < GK; k++) {
            float4 w = sW4[k * 16 + tx];
            unsigned long long w01, w23;
            asm("mov.b64 %0, {%1,%2};" : "=l"(w01) : "f"(w.x), "f"(w.y));
            asm("mov.b64 %0, {%1,%2};" : "=l"(w23) : "f"(w.z), "f"(w.w));
            float4 xa = *(const float4*)(&sxT[k][ty8]);
            float4 xb = *(const float4*)(&sxT[k][ty8 + 4]);
            unsigned long long xx;
            SPLAT2(xx, xa.x); FMA2(accA[0], w01, xx); FMA2(accB[0], w23, xx);
            SPLAT2(xx, xa.y); FMA2(accA[1], w01, xx); FMA2(accB[1], w23, xx);
            SPLAT2(xx, xa.z); FMA2(accA[2], w01, xx); FMA2(accB[2], w23, xx);
            SPLAT2(xx, xa.w); FMA2(accA[3], w01, xx); FMA2(accB[3], w23, xx);
            SPLAT2(xx, xb.x); FMA2(accA[4], w01, xx); FMA2(accB[4], w23, xx);
            SPLAT2(xx, xb.y); FMA2(accA[5], w01, xx); FMA2(accB[5], w23, xx);
            SPLAT2(xx, xb.z); FMA2(accA[6], w01, xx); FMA2(accB[6], w23, xx);
            SPLAT2(xx, xb.w); FMA2(accA[7], w01, xx); FMA2(accB[7], w23, xx);
        }
        __syncthreads();
    }
}

__device__ __forceinline__ void gemm_epilogue(int n0, int tx, int ty8,
                                              const unsigned long long* accA,
                                              const unsigned long long* accB) {
    #pragma unroll
    for (int i = 0; i < 8; i++) {
        int n = n0 + ty8 + i;
        if (n < N_NODES) {
            float dc = rsqrtf((float)(g_deg[n] + 1));
            float f0, f1, f2, f3;
            UNPACKF(f0, f1, accA[i]);
            UNPACKF(f2, f3, accB[i]);
            ((float4*)g_g)[n * 16 + tx] = make_float4(f0 * dc, f1 * dc, f2 * dc, f3 * dc);
        }
    }
}

// ---------------- conv1 = prep (grid-stride slice) + device barrier + gemm1 ----------------
// Barrier is deadlock-free: 391 blocks @ 64 regs/25KB smem/256thr -> 4 blocks/SM
// (592 concurrent capacity on 148+ SMs), so all blocks are resident in wave 1.
__global__ void __launch_bounds__(256, 4)
k_conv1(const float* __restrict__ x, const float* __restrict__ W1,
        const void* __restrict__ ei, const void* __restrict__ batch) {
    __shared__ float sxT[GK][GNP];
    __shared__ float sW[GK * HID];
    int t = threadIdx.x;

    // ---- phase 1: prep slice ----
    __shared__ int s_any;
    if (t == 0) s_any = 0;
    __syncthreads();
    {
        const int* p32 = (const int*)ei;
        int v = p32[2 * t + 1];   // ids < 50000: int64 => odd words all zero
        if (v) atomicOr(&s_any, 1);
    }
    __syncthreads();
    int is64 = (s_any == 0) ? 1 : 0;

    const int NT = GB1 * 256;
    for (int e = blockIdx.x * 256 + t; e < N_EDGES; e += NT) {
        int r, c;
        if (is64) {
            const long long* p = (const long long*)ei;
            r = (int)p[e];
            c = (int)p[N_EDGES + e];
        } else {
            const int* p = (const int*)ei;
            r = p[e];
            c = p[N_EDGES + e];
        }
        int pos = atomicAdd(&g_deg[c], 1);
        if (pos < MAXDEG) g_adj[c * MAXDEG + pos] = r;
    }
    for (int i = blockIdx.x * 256 + t; i < N_NODES; i += NT) {
        int b = is64 ? (int)((const long long*)batch)[i] : ((const int*)batch)[i];
        g_batch[i] = b;
        atomicAdd(&g_cnt[b], 1);
    }
    __threadfence();          // release adj/batch/deg writes
    __syncthreads();
    if (t == 0) atomicAdd(&g_c1, 1);

    // ---- phase 2: GEMM main loop (inputs only; overlaps other blocks' prep) ----
    int n0 = blockIdx.x * GNT;
    int tx = t & 15;
    int ty8 = (t >> 4) * 8;
    unsigned long long accA[8], accB[8];
    #pragma unroll
    for (int i = 0; i < 8; i++) { accA[i] = 0ULL; accB[i] = 0ULL; }
    gemm_main<IN_DIM>(x, W1, sxT, sW, n0, tx, ty8, accA, accB);

    // ---- phase 3: wait for all prep slices, then deg-dependent epilogue ----
    if (t == 0) {
        while (atomicAdd(&g_c1, 0) < GB1) __nanosleep(64);
    }
    __syncthreads();
    __threadfence();          // acquire
    gemm_epilogue(n0, tx, ty8, accA, accB);
}

// ---------------- gemm2 (plain): g_g = dinv * (g_a @ W2) ----------------
__global__ void __launch_bounds__(256, 4)
k_gemm2(const float* __restrict__ W2) {
    __shared__ float sxT[GK][GNP];
    __shared__ float sW[GK * HID];
    int t = threadIdx.x;
    int n0 = blockIdx.x * GNT;
    int tx = t & 15;
    int ty8 = (t >> 4) * 8;
    unsigned long long accA[8], accB[8];
    #pragma unroll
    for (int i = 0; i < 8; i++) { accA[i] = 0ULL; accB[i] = 0ULL; }
    gemm_main<HID>((const float*)g_a, W2, sxT, sW, n0, tx, ty8, accA, accB);
    gemm_epilogue(n0, tx, ty8, accA, accB);
}

// ---------------- gather (R10-proven plain float4 form) ----------------
__device__ __forceinline__ float4 gather_region(const float4* __restrict__ G4, int fq, int half,
                                                int areg, int len, float4 acc) {
    int i = 0;
    for (; i + 8 <= len; i += 8) {
        int e0 = __shfl_sync(0xFFFFFFFFu, areg, i + 0 + half);
        int e1 = __shfl_sync(0xFFFFFFFFu, areg, i + 2 + half);
        int e2 = __shfl_sync(0xFFFFFFFFu, areg, i + 4 + half);
        int e3 = __shfl_sync(0xFFFFFFFFu, areg, i + 6 + half);
        float4 v0 = G4[e0 * 16 + fq];
        float4 v1 = G4[e1 * 16 + fq];
        float4 v2 = G4[e2 * 16 + fq];
        float4 v3 = G4[e3 * 16 + fq];
        acc.x += (v0.x + v1.x) + (v2.x + v3.x);
        acc.y += (v0.y + v1.y) + (v2.y + v3.y);
        acc.z += (v0.z + v1.z) + (v2.z + v3.z);
        acc.w += (v0.w + v1.w) + (v2.w + v3.w);
    }
    for (; i + 2 <= len; i += 2) {
        int e = __shfl_sync(0xFFFFFFFFu, areg, i + half);
        float4 v = G4[e * 16 + fq];
        acc.x += v.x; acc.y += v.y; acc.z += v.z; acc.w += v.w;
    }
    if (i < len) {
        int e = __shfl_sync(0xFFFFFFFFu, areg, i);
        if (half == 0) {
            float4 v = G4[e * 16 + fq];
            acc.x += v.x; acc.y += v.y; acc.z += v.z; acc.w += v.w;
        }
    }
    return acc;
}

__device__ __forceinline__ float4 gather_sum4(int node, int lane, int d) {
    int half = lane >> 4;
    int fq   = lane & 15;
    const float4* G4 = (const float4*)g_g;
    const int* adj = &g_adj[node * MAXDEG];
    int a0 = (lane < d)      ? adj[lane]      : 0;
    int a1 = (32 + lane < d) ? adj[32 + lane] : 0;
    float4 acc = make_float4(0.f, 0.f, 0.f, 0.f);
    if (half == 0) acc = G4[node * 16 + fq];
    int d0 = min(d, 32);
    acc = gather_region(G4, fq, half, a0, d0, acc);
    if (d > 32) acc = gather_region(G4, fq, half, a1, d - 32, acc);
    acc.x += __shfl_xor_sync(0xFFFFFFFFu, acc.x, 16);
    acc.y += __shfl_xor_sync(0xFFFFFFFFu, acc.y, 16);
    acc.z += __shfl_xor_sync(0xFFFFFFFFu, acc.z, 16);
    acc.w += __shfl_xor_sync(0xFFFFFFFFu, acc.w, 16);
    return acc;
}

// ---------------- agg1: gather over g_g + relu -> g_a ----------------
__global__ void k_agg1(const float* __restrict__ b) {
    int warp = (blockIdx.x * blockDim.x + threadIdx.x) >> 5;
    if (warp >= N_NODES) return;
    int lane = threadIdx.x & 31;
    int d = min(g_deg[warp], MAXDEG);
    float4 acc = gather_sum4(warp, lane, d);
    if (lane < 16) {
        float dc = rsqrtf((float)(d + 1));
        float4 bb = ((const float4*)b)[lane];
        float4 o;
        o.x = fmaxf(acc.x * dc + bb.x, 0.f);
        o.y = fmaxf(acc.y * dc + bb.y, 0.f);
        o.z = fmaxf(acc.z * dc + bb.z, 0.f);
        o.w = fmaxf(acc.w * dc + bb.w, 0.f);
        ((float4*)g_a)[warp * 16 + lane] = o;
    }
}

// ---------------- agg2: gather over g_g + relu, RED straight into pool ----------------
__global__ void k_agg2(const float* __restrict__ b) {
    int warp = (blockIdx.x * blockDim.x + threadIdx.x) >> 5;
    if (warp >= N_NODES) return;
    int lane = threadIdx.x & 31;
    int d = min(g_deg[warp], MAXDEG);
    float4 acc = gather_sum4(warp, lane, d);
    if (lane < 16) {
        float dc = rsqrtf((float)(d + 1));
        float4 bb = ((const float4*)b)[lane];
        float ox = fmaxf(acc.x * dc + bb.x, 0.f);
        float oy = fmaxf(acc.y * dc + bb.y, 0.f);
        float oz = fmaxf(acc.z * dc + bb.z, 0.f);
        float ow = fmaxf(acc.w * dc + bb.w, 0.f);
        int gid = g_batch[warp];
        float* dst = &g_pool[gid * HID + lane * 4];
        asm volatile("red.global.add.v4.f32 [%0], {%1,%2,%3,%4};"
                     :: "l"(dst), "f"(ox), "f"(oy), "f"(oz), "f"(ow) : "memory");
    }
}

// ---------------- final: logits + log_softmax, then restore the zero-invariant ----------------
__global__ void k_final(const float* __restrict__ Wl, const float* __restrict__ bl,
                        float* __restrict__ out) {
    if (blockIdx.x == 0 && threadIdx.x < N_GRAPHS) {
        int gph = threadIdx.x;
        float cnt = fmaxf((float)g_cnt[gph], 1.f);
        float inv = 1.f / cnt;
        float l0 = bl[0], l1 = bl[1];
        #pragma unroll
        for (int k = 0; k < HID; k++) {
            float p = g_pool[gph * HID + k] * inv;
            l0 += p * Wl[k * 2 + 0];
            l1 += p * Wl[k * 2 + 1];
        }
        float m = fmaxf(l0, l1);
        float lse = m + logf(expf(l0 - m) + expf(l1 - m));
        out[gph * 2 + 0] = l0 - lse;
        out[gph * 2 + 1] = l1 - lse;
        // this thread owns pool row gph and cnt[gph]; zero them after reading
        float4 z4 = make_float4(0.f, 0.f, 0.f, 0.f);
        #pragma unroll
        for (int k = 0; k < HID / 4; k++) ((float4*)g_pool)[gph * 16 + k] = z4;
        g_cnt[gph] = 0;
    }
    if (blockIdx.x == 0 && threadIdx.x == 0) g_c1 = 0;
    // all blocks: zero deg for the next call
    int gid = blockIdx.x * blockDim.x + threadIdx.x;
    for (int j = gid; j < N_NODES; j += gridDim.x * blockDim.x) g_deg[j] = 0;
}

extern "C" void kernel_launch(void* const* d_in, const int* in_sizes, int n_in,
                              void* d_out, int out_size) {
    const float* x  = (const float*)d_in[0];
    const void*  ei = d_in[1];
    const void*  bt = d_in[2];
    const float* W1 = (const float*)d_in[3];
    const float* b1 = (const float*)d_in[4];
    const float* W2 = (const float*)d_in[5];
    const float* b2 = (const float*)d_in[6];
    const float* Wl = (const float*)d_in[7];
    const float* bl = (const float*)d_in[8];
    float* out = (float*)d_out;

    // conv1: prep + barrier + linear (x @ W1, pre-scaled)
    k_conv1<<<GB1, 256>>>(x, W1, ei, bt);
    // conv1 aggregate + relu
    k_agg1<<<(N_NODES * 32 + 255) / 256, 256>>>(b1);
    // conv2 linear
    k_gemm2<<<GB1, 256>>>(W2);
    // conv2 aggregate + relu + pool
    k_agg2<<<(N_NODES * 32 + 255) / 256, 256>>>(b2);
    // head + cleanup (restores zero-invariant for deg/pool/cnt/c1)
    k_final<<<196, 256>>>(Wl, bl, out);
}

// round 17
// speedup vs baseline: 1.2537x; 1.1261x over previous
#include <cuda_runtime.h>
#include <cuda_bf16.h>

#define N_NODES 50000
#define N_EDGES 800000
#define IN_DIM  128
#define HID     64
#define N_GRAPHS 64
#define MAXDEG  64   // P(Poisson(16) > 64) ~ 1e-17 per node; safe

// ---------------- device scratch ----------------
// INVARIANT at entry to kernel_launch (established at module load, restored by
// k_final every call): g_deg == 0, g_pool == 0, g_cnt == 0, g_c1 == 0.
__device__ float g_g[N_NODES * HID];      // GEMM output payload (both layers)
__device__ float g_a[N_NODES * HID];      // conv1 activation
__device__ int   g_deg[N_NODES];
__device__ int   g_adj[N_NODES * MAXDEG]; // bucket adjacency: sources per target
__device__ int   g_batch[N_NODES];
__device__ float g_pool[N_GRAPHS * HID];
__device__ int   g_cnt[N_GRAPHS];
__device__ int   g_c1;                    // conv1 prep-phase arrive counter

#define GK  32     // K chunk
#define GNT 128    // node tile
#define GNP 132    // padded stride for sxT rows
#define GB1 ((N_NODES + GNT - 1) / GNT)   // 391 blocks for both GEMMs
#define AGG2_BLOCKS (N_NODES / 8)         // 6250, exact: no partial blocks

#define SPLAT2(dst, s) asm("mov.b64 %0, {%1,%1};" : "=l"(dst) : "r"(__float_as_uint(s)))
#define FMA2(acc, a, b) asm("fma.rn.f32x2 %0, %1, %2, %0;" : "+l"(acc) : "l"(a), "l"(b))
#define UNPACKF(a, b, src) asm("mov.b64 {%0, %1}, %2;" : "=f"(a), "=f"(b) : "l"(src))

// ---------------- shared GEMM main loop (reads only X, W) ----------------
template<int K>
__device__ __forceinline__ void gemm_main(const float* __restrict__ X,
                                          const float* __restrict__ W,
                                          float (*sxT)[GNP], float* sW,
                                          int n0, int tx, int ty8,
                                          unsigned long long* accA, unsigned long long* accB) {
    int t = threadIdx.x;
    for (int kc = 0; kc < K; kc += GK) {
        {
            const float4* Wg = (const float4*)(W + kc * HID);
            float4* sW4 = (float4*)sW;
            sW4[t]       = Wg[t];
            sW4[t + 256] = Wg[t + 256];
        }
        #pragma unroll
        for (int j = t; j < 1024; j += 256) {
            int node = j >> 3;
            int k4 = (j & 7) * 4;
            int gn = n0 + node;
            float4 v = (gn < N_NODES) ? ((const float4*)(X + gn * K + kc))[j & 7]
                                      : make_float4(0.f, 0.f, 0.f, 0.f);
            sxT[k4 + 0][node] = v.x;
            sxT[k4 + 1][node] = v.y;
            sxT[k4 + 2][node] = v.z;
            sxT[k4 + 3][node] = v.w;
        }
        __syncthreads();
        const float4* sW4 = (const float4*)sW;
        #pragma unroll 8
        for (int k = 0; k < GK; k++) {
            float4 w = sW4[k * 16 + tx];
            unsigned long long w01, w23;
            asm("mov.b64 %0, {%1,%2};" : "=l"(w01) : "f"(w.x), "f"(w.y));
            asm("mov.b64 %0, {%1,%2};" : "=l"(w23) : "f"(w.z), "f"(w.w));
            float4 xa = *(const float4*)(&sxT[k][ty8]);
            float4 xb = *(const float4*)(&sxT[k][ty8 + 4]);
            unsigned long long xx;
            SPLAT2(xx, xa.x); FMA2(accA[0], w01, xx); FMA2(accB[0], w23, xx);
            SPLAT2(xx, xa.y); FMA2(accA[1], w01, xx); FMA2(accB[1], w23, xx);
            SPLAT2(xx, xa.z); FMA2(accA[2], w01, xx); FMA2(accB[2], w23, xx);
            SPLAT2(xx, xa.w); FMA2(accA[3], w01, xx); FMA2(accB[3], w23, xx);
            SPLAT2(xx, xb.x); FMA2(accA[4], w01, xx); FMA2(accB[4], w23, xx);
            SPLAT2(xx, xb.y); FMA2(accA[5], w01, xx); FMA2(accB[5], w23, xx);
            SPLAT2(xx, xb.z); FMA2(accA[6], w01, xx); FMA2(accB[6], w23, xx);
            SPLAT2(xx, xb.w); FMA2(accA[7], w01, xx); FMA2(accB[7], w23, xx);
        }
        __syncthreads();
    }
}

__device__ __forceinline__ void gemm_epilogue(int n0, int tx, int ty8,
                                              const unsigned long long* accA,
                                              const unsigned long long* accB) {
    #pragma unroll
    for (int i = 0; i < 8; i++) {
        int n = n0 + ty8 + i;
        if (n < N_NODES) {
            float dc = rsqrtf((float)(g_deg[n] + 1));
            float f0, f1, f2, f3;
            UNPACKF(f0, f1, accA[i]);
            UNPACKF(f2, f3, accB[i]);
            ((float4*)g_g)[n * 16 + tx] = make_float4(f0 * dc, f1 * dc, f2 * dc, f3 * dc);
        }
    }
}

// ---------------- conv1 = prep (grid-stride slice) + device barrier + gemm1 ----------------
// Barrier is deadlock-free: 391 blocks @ 64 regs/25KB smem/256thr -> 4 blocks/SM
// (592 concurrent capacity on 148+ SMs), so all blocks are resident in wave 1.
__global__ void __launch_bounds__(256, 4)
k_conv1(const float* __restrict__ x, const float* __restrict__ W1,
        const void* __restrict__ ei, const void* __restrict__ batch) {
    __shared__ float sxT[GK][GNP];
    __shared__ float sW[GK * HID];
    int t = threadIdx.x;

    // ---- phase 1: prep slice ----
    __shared__ int s_any;
    if (t == 0) s_any = 0;
    __syncthreads();
    {
        const int* p32 = (const int*)ei;
        int v = p32[2 * t + 1];   // ids < 50000: int64 => odd words all zero
        if (v) atomicOr(&s_any, 1);
    }
    __syncthreads();
    int is64 = (s_any == 0) ? 1 : 0;

    const int NT = GB1 * 256;
    for (int e = blockIdx.x * 256 + t; e < N_EDGES; e += NT) {
        int r, c;
        if (is64) {
            const long long* p = (const long long*)ei;
            r = (int)p[e];
            c = (int)p[N_EDGES + e];
        } else {
            const int* p = (const int*)ei;
            r = p[e];
            c = p[N_EDGES + e];
        }
        int pos = atomicAdd(&g_deg[c], 1);
        if (pos < MAXDEG) g_adj[c * MAXDEG + pos] = r;
    }
    for (int i = blockIdx.x * 256 + t; i < N_NODES; i += NT) {
        int b = is64 ? (int)((const long long*)batch)[i] : ((const int*)batch)[i];
        g_batch[i] = b;
        atomicAdd(&g_cnt[b], 1);
    }
    __threadfence();          // release adj/batch/deg writes
    __syncthreads();
    if (t == 0) atomicAdd(&g_c1, 1);

    // ---- phase 2: GEMM main loop (inputs only; overlaps other blocks' prep) ----
    int n0 = blockIdx.x * GNT;
    int tx = t & 15;
    int ty8 = (t >> 4) * 8;
    unsigned long long accA[8], accB[8];
    #pragma unroll
    for (int i = 0; i < 8; i++) { accA[i] = 0ULL; accB[i] = 0ULL; }
    gemm_main<IN_DIM>(x, W1, sxT, sW, n0, tx, ty8, accA, accB);

    // ---- phase 3: wait for all prep slices, then deg-dependent epilogue ----
    if (t == 0) {
        while (atomicAdd(&g_c1, 0) < GB1) __nanosleep(64);
    }
    __syncthreads();
    __threadfence();          // acquire
    gemm_epilogue(n0, tx, ty8, accA, accB);
}

// ---------------- gemm2 (plain): g_g = dinv * (g_a @ W2) ----------------
__global__ void __launch_bounds__(256, 4)
k_gemm2(const float* __restrict__ W2) {
    __shared__ float sxT[GK][GNP];
    __shared__ float sW[GK * HID];
    int t = threadIdx.x;
    int n0 = blockIdx.x * GNT;
    int tx = t & 15;
    int ty8 = (t >> 4) * 8;
    unsigned long long accA[8], accB[8];
    #pragma unroll
    for (int i = 0; i < 8; i++) { accA[i] = 0ULL; accB[i] = 0ULL; }
    gemm_main<HID>((const float*)g_a, W2, sxT, sW, n0, tx, ty8, accA, accB);
    gemm_epilogue(n0, tx, ty8, accA, accB);
}

// ---------------- gather (R10-proven plain float4 form) ----------------
__device__ __forceinline__ float4 gather_region(const float4* __restrict__ G4, int fq, int half,
                                                int areg, int len, float4 acc) {
    int i = 0;
    for (; i + 8 <= len; i += 8) {
        int e0 = __shfl_sync(0xFFFFFFFFu, areg, i + 0 + half);
        int e1 = __shfl_sync(0xFFFFFFFFu, areg, i + 2 + half);
        int e2 = __shfl_sync(0xFFFFFFFFu, areg, i + 4 + half);
        int e3 = __shfl_sync(0xFFFFFFFFu, areg, i + 6 + half);
        float4 v0 = G4[e0 * 16 + fq];
        float4 v1 = G4[e1 * 16 + fq];
        float4 v2 = G4[e2 * 16 + fq];
        float4 v3 = G4[e3 * 16 + fq];
        acc.x += (v0.x + v1.x) + (v2.x + v3.x);
        acc.y += (v0.y + v1.y) + (v2.y + v3.y);
        acc.z += (v0.z + v1.z) + (v2.z + v3.z);
        acc.w += (v0.w + v1.w) + (v2.w + v3.w);
    }
    for (; i + 2 <= len; i += 2) {
        int e = __shfl_sync(0xFFFFFFFFu, areg, i + half);
        float4 v = G4[e * 16 + fq];
        acc.x += v.x; acc.y += v.y; acc.z += v.z; acc.w += v.w;
    }
    if (i < len) {
        int e = __shfl_sync(0xFFFFFFFFu, areg, i);
        if (half == 0) {
            float4 v = G4[e * 16 + fq];
            acc.x += v.x; acc.y += v.y; acc.z += v.z; acc.w += v.w;
        }
    }
    return acc;
}

__device__ __forceinline__ float4 gather_sum4(int node, int lane, int d) {
    int half = lane >> 4;
    int fq   = lane & 15;
    const float4* G4 = (const float4*)g_g;
    const int* adj = &g_adj[node * MAXDEG];
    int a0 = (lane < d)      ? adj[lane]      : 0;
    int a1 = (32 + lane < d) ? adj[32 + lane] : 0;
    float4 acc = make_float4(0.f, 0.f, 0.f, 0.f);
    if (half == 0) acc = G4[node * 16 + fq];
    int d0 = min(d, 32);
    acc = gather_region(G4, fq, half, a0, d0, acc);
    if (d > 32) acc = gather_region(G4, fq, half, a1, d - 32, acc);
    acc.x += __shfl_xor_sync(0xFFFFFFFFu, acc.x, 16);
    acc.y += __shfl_xor_sync(0xFFFFFFFFu, acc.y, 16);
    acc.z += __shfl_xor_sync(0xFFFFFFFFu, acc.z, 16);
    acc.w += __shfl_xor_sync(0xFFFFFFFFu, acc.w, 16);
    return acc;
}

// ---------------- agg1: gather over g_g + relu -> g_a ----------------
__global__ void k_agg1(const float* __restrict__ b) {
    int warp = (blockIdx.x * blockDim.x + threadIdx.x) >> 5;
    if (warp >= N_NODES) return;
    int lane = threadIdx.x & 31;
    int d = min(g_deg[warp], MAXDEG);
    float4 acc = gather_sum4(warp, lane, d);
    if (lane < 16) {
        float dc = rsqrtf((float)(d + 1));
        float4 bb = ((const float4*)b)[lane];
        float4 o;
        o.x = fmaxf(acc.x * dc + bb.x, 0.f);
        o.y = fmaxf(acc.y * dc + bb.y, 0.f);
        o.z = fmaxf(acc.z * dc + bb.z, 0.f);
        o.w = fmaxf(acc.w * dc + bb.w, 0.f);
        ((float4*)g_a)[warp * 16 + lane] = o;
    }
}

// ---------------- agg2: gather + relu; batch-sorted run-merge in smem, then pool RED ----
// batch is sorted, so the 8 nodes of a block span 1-2 graphs: REDs drop 800k -> ~105k.
__global__ void k_agg2(const float* __restrict__ b) {
    __shared__ float4 s_feat[8][16];   // per-warp relu'd row
    __shared__ int    s_gid[8];
    int wid  = threadIdx.x >> 5;
    int warp = blockIdx.x * 8 + wid;   // grid exactly N_NODES/8: all warps valid
    int lane = threadIdx.x & 31;
    int d = min(g_deg[warp], MAXDEG);
    float4 acc = gather_sum4(warp, lane, d);
    if (lane < 16) {
        float dc = rsqrtf((float)(d + 1));
        float4 bb = ((const float4*)b)[lane];
        float4 o;
        o.x = fmaxf(acc.x * dc + bb.x, 0.f);
        o.y = fmaxf(acc.y * dc + bb.y, 0.f);
        o.z = fmaxf(acc.z * dc + bb.z, 0.f);
        o.w = fmaxf(acc.w * dc + bb.w, 0.f);
        s_feat[wid][lane] = o;
    }
    if (lane == 0) s_gid[wid] = g_batch[warp];
    __syncthreads();

    int t = threadIdx.x;
    if (t < 16) {   // thread t owns float4 slot t (features 4t..4t+3)
        float4 r = make_float4(0.f, 0.f, 0.f, 0.f);
        int cur = s_gid[0];
        #pragma unroll
        for (int j = 0; j < 8; j++) {
            int gid = s_gid[j];
            if (gid != cur) {
                asm volatile("red.global.add.v4.f32 [%0], {%1,%2,%3,%4};"
                             :: "l"(&g_pool[cur * HID + t * 4]),
                                "f"(r.x), "f"(r.y), "f"(r.z), "f"(r.w) : "memory");
                r = make_float4(0.f, 0.f, 0.f, 0.f);
                cur = gid;
            }
            float4 v = s_feat[j][t];
            r.x += v.x; r.y += v.y; r.z += v.z; r.w += v.w;
        }
        asm volatile("red.global.add.v4.f32 [%0], {%1,%2,%3,%4};"
                     :: "l"(&g_pool[cur * HID + t * 4]),
                        "f"(r.x), "f"(r.y), "f"(r.z), "f"(r.w) : "memory");
    }
}

// ---------------- final: logits + log_softmax, then restore the zero-invariant ----------------
__global__ void k_final(const float* __restrict__ Wl, const float* __restrict__ bl,
                        float* __restrict__ out) {
    if (blockIdx.x == 0 && threadIdx.x < N_GRAPHS) {
        int gph = threadIdx.x;
        float cnt = fmaxf((float)g_cnt[gph], 1.f);
        float inv = 1.f / cnt;
        float l0 = bl[0], l1 = bl[1];
        #pragma unroll
        for (int k = 0; k < HID; k++) {
            float p = g_pool[gph * HID + k] * inv;
            l0 += p * Wl[k * 2 + 0];
            l1 += p * Wl[k * 2 + 1];
        }
        float m = fmaxf(l0, l1);
        float lse = m + logf(expf(l0 - m) + expf(l1 - m));
        out[gph * 2 + 0] = l0 - lse;
        out[gph * 2 + 1] = l1 - lse;
        // this thread owns pool row gph and cnt[gph]; zero them after reading
        float4 z4 = make_float4(0.f, 0.f, 0.f, 0.f);
        #pragma unroll
        for (int k = 0; k < HID / 4; k++) ((float4*)g_pool)[gph * 16 + k] = z4;
        g_cnt[gph] = 0;
    }
    if (blockIdx.x == 0 && threadIdx.x == 0) g_c1 = 0;
    // all blocks: zero deg for the next call
    int gid = blockIdx.x * blockDim.x + threadIdx.x;
    for (int j = gid; j < N_NODES; j += gridDim.x * blockDim.x) g_deg[j] = 0;
}

extern "C" void kernel_launch(void* const* d_in, const int* in_sizes, int n_in,
                              void* d_out, int out_size) {
    const float* x  = (const float*)d_in[0];
    const void*  ei = d_in[1];
    const void*  bt = d_in[2];
    const float* W1 = (const float*)d_in[3];
    const float* b1 = (const float*)d_in[4];
    const float* W2 = (const float*)d_in[5];
    const float* b2 = (const float*)d_in[6];
    const float* Wl = (const float*)d_in[7];
    const float* bl = (const float*)d_in[8];
    float* out = (float*)d_out;

    // conv1: prep + barrier + linear (x @ W1, pre-scaled)
    k_conv1<<<GB1, 256>>>(x, W1, ei, bt);
    // conv1 aggregate + relu
    k_agg1<<<(N_NODES * 32 + 255) / 256, 256>>>(b1);
    // conv2 linear
    k_gemm2<<<GB1, 256>>>(W2);
    // conv2 aggregate + relu + pool (batch-sorted run-merge)
    k_agg2<<<AGG2_BLOCKS, 256>>>(b2);
    // head + cleanup (restores zero-invariant for deg/pool/cnt/c1)
    k_final<<<196, 256>>>(Wl, bl, out);
}